// round 3
// baseline (speedup 1.0000x reference)
#include <cuda_runtime.h>

#define TAPS 343

// phase-split s: [n][pz][py][px][c=4][32][32][32]  (64 MB)
__device__ float g_s[16*8*4*32*32*32];
// phase-split v: [n][pz][py][px][c=24][17][17][17] (60.4 MB)
__device__ float g_v[16*8*24*17*17*17];
// y pre-BN: [n][16][19][19][19] (7 MB)
__device__ float g_y[16*16*19*19*19];
__device__ float g_sum[16];
__device__ float g_sumsq[16];

__global__ void k_zero() {
    int i = threadIdx.x;
    if (i < 16) { g_sum[i] = 0.f; g_sumsq[i] = 0.f; }
}

// repack s (NCDHW 64^3) into parity-split layout; coalesced read side.
__global__ void k_split(const float* __restrict__ s) {
    int i = blockIdx.x * 256 + threadIdx.x;          // 2^24 total
    int x = i & 63;
    int y = (i >> 6) & 63;
    int z = (i >> 12) & 63;
    int c = (i >> 18) & 3;
    int n = i >> 20;
    int pp = ((((n * 2 + (z & 1)) * 2 + (y & 1)) * 2 + (x & 1)) * 4 + c);
    g_s[pp * 32768 + ((z >> 1) * 32 + (y >> 1)) * 32 + (x >> 1)] = s[i];
}

// conv1: s[4ch] --(9 basis filters, stride2 pad5)--> 36 basis responses,
// then mix with W1 -> v[24ch], stored parity-split.
// Block tile: 8(ox) x 4(oy) x 8(oz); 128 threads, 2 oz positions per thread.
__global__ __launch_bounds__(128) void k_conv1(const float* __restrict__ basis1,
                                               const float* __restrict__ W1) {
    __shared__ float kb[9 * TAPS];   // [f = b*3+i][tap]  (same linear layout as basis1)
    __shared__ float w1[96];
    int tid = threadIdx.x;
    for (int i = tid; i < 9 * TAPS; i += 128) kb[i] = basis1[i];
    if (tid < 96) w1[tid] = W1[tid];
    __syncthreads();

    int bx = blockIdx.x;                  // grid.x = 5(x)*9(y)*5(z) = 225
    int txi = bx % 5, tyi = (bx / 5) % 9, tzi = bx / 45;
    int n = blockIdx.y;
    int lx = tid & 7, ly = (tid >> 3) & 3, lz = tid >> 5;
    int ox = txi * 8 + lx, oy = tyi * 4 + ly, oz = tzi * 8 + lz;

    float acc[72];
#pragma unroll
    for (int i = 0; i < 72; i++) acc[i] = 0.f;

    int bxx = 2 * ox - 5, byy = 2 * oy - 5, bzz = 2 * oz - 5;
    for (int kz = 0; kz < 7; kz++) {
        int iz = bzz + kz;
        int pz = iz & 1, z2 = iz >> 1;
        bool vzA = (unsigned)z2 < 32u;
        bool vzB = (unsigned)(z2 + 4) < 32u;   // second position: oz+4 -> iz+8 -> z2+4
        for (int ky = 0; ky < 7; ky++) {
            int iy = byy + ky;
            int py = iy & 1, y2 = iy >> 1;
            bool vy = (unsigned)y2 < 32u;
            int tapzy = (kz * 7 + ky) * 7;
#pragma unroll
            for (int kx = 0; kx < 7; kx++) {
                int ix = bxx + kx;
                int px = ix & 1, x2 = ix >> 1;
                bool vx = (unsigned)x2 < 32u;
                int tap = tapzy + kx;
                float kr[9];
#pragma unroll
                for (int f = 0; f < 9; f++) kr[f] = kb[f * TAPS + tap];
                bool vA = vzA && vy && vx;
                bool vB = vzB && vy && vx;
                int pbase = (((n * 2 + pz) * 2 + py) * 2 + px) * 4;
                int sp = (z2 * 32 + y2) * 32 + x2;
#pragma unroll
                for (int c = 0; c < 4; c++) {
                    const float* p = g_s + (pbase + c) * 32768;
                    float sA = vA ? p[sp] : 0.f;
                    float sB = vB ? p[sp + 4096] : 0.f;   // z2+4 plane
#pragma unroll
                    for (int f = 0; f < 9; f++) {
                        acc[c * 9 + f]      = fmaf(sA, kr[f], acc[c * 9 + f]);
                        acc[36 + c * 9 + f] = fmaf(sB, kr[f], acc[36 + c * 9 + f]);
                    }
                }
            }
        }
    }

    // mix (24 out = sum over v,b of W1 * basis response) and store parity-split v
#pragma unroll
    for (int pos = 0; pos < 2; pos++) {
        int ozp = oz + pos * 4;
        if (ox < 34 && oy < 34 && ozp < 34) {
            int pp = ((ozp & 1) * 2 + (oy & 1)) * 2 + (ox & 1);
            long long base = (long long)((n * 8 + pp) * 24) * 4913
                           + ((ozp >> 1) * 17 + (oy >> 1)) * 17 + (ox >> 1);
#pragma unroll
            for (int u = 0; u < 8; u++) {
#pragma unroll
                for (int i3 = 0; i3 < 3; i3++) {
                    float r = 0.f;
#pragma unroll
                    for (int v = 0; v < 4; v++)
#pragma unroll
                        for (int b = 0; b < 3; b++)
                            r = fmaf(w1[u * 12 + v * 3 + b],
                                     acc[pos * 36 + v * 9 + b * 3 + i3], r);
                    g_v[base + (u * 3 + i3) * 4913] = r;
                }
            }
        }
    }
}

// conv2: v (24ch) + on-the-fly tensor product (72ch) -> basis responses da[8][3], db[8][3],
// mixed with W2a/W2b -> y[16]; accumulates BN stats.
// Block tile: 8(ox) x 4(oy) x 4(oz) = 128 positions, 1/thread.
__global__ __launch_bounds__(128) void k_conv2(const float* __restrict__ b2a,
                                               const float* __restrict__ b2b,
                                               const float* __restrict__ w2a_g,
                                               const float* __restrict__ w2b_g) {
    __shared__ float A[9 * TAPS];     // [b*3+j][tap]
    __shared__ float Bs[18 * TAPS];   // symmetrized: [b*6+p][tap], p over (00,11,22,01,02,12)
    __shared__ float w2a[384];
    __shared__ float w2b[384];
    int tid = threadIdx.x;
    for (int i = tid; i < 9 * TAPS; i += 128) A[i] = b2a[i];
    for (int i = tid; i < 18 * TAPS; i += 128) {
        int row = i / TAPS, tap = i - row * TAPS;
        int b = row / 6, p = row % 6;
        float v;
        if (p < 3)       v = b2b[(b * 9 + p * 4) * TAPS + tap];                       // diag jj = p*3+p
        else if (p == 3) v = b2b[(b * 9 + 1) * TAPS + tap] + b2b[(b * 9 + 3) * TAPS + tap];
        else if (p == 4) v = b2b[(b * 9 + 2) * TAPS + tap] + b2b[(b * 9 + 6) * TAPS + tap];
        else             v = b2b[(b * 9 + 5) * TAPS + tap] + b2b[(b * 9 + 7) * TAPS + tap];
        Bs[i] = v;
    }
    for (int i = tid; i < 384; i += 128) { w2a[i] = w2a_g[i]; w2b[i] = w2b_g[i]; }
    __syncthreads();

    int bx = blockIdx.x;                   // grid.x = 3(x)*5(y)*5(z) = 75
    int txi = bx % 3, tyi = (bx / 3) % 5, tzi = bx / 15;
    int n = blockIdx.y;
    int lx = tid & 7, ly = (tid >> 3) & 3, lzt = tid >> 5;
    int ox = txi * 8 + lx, oy = tyi * 4 + ly, oz = tzi * 4 + lzt;

    float da[24], db[24];
#pragma unroll
    for (int i = 0; i < 24; i++) { da[i] = 0.f; db[i] = 0.f; }

    int bxx = 2 * ox - 5, byy = 2 * oy - 5, bzz = 2 * oz - 5;
    for (int kz = 0; kz < 7; kz++) {
        int iz = bzz + kz;
        int pz = iz & 1, z2 = iz >> 1;
        bool vz = (unsigned)z2 < 17u;
        for (int ky = 0; ky < 7; ky++) {
            int iy = byy + ky;
            int py = iy & 1, y2 = iy >> 1;
            bool vy = (unsigned)y2 < 17u;
            int tapzy = (kz * 7 + ky) * 7;
#pragma unroll
            for (int kx = 0; kx < 7; kx++) {
                int ix = bxx + kx;
                int px = ix & 1, x2 = ix >> 1;
                bool vv = vz && vy && ((unsigned)x2 < 17u);
                int tap = tapzy + kx;
                float ar[9];
#pragma unroll
                for (int f = 0; f < 9; f++) ar[f] = A[f * TAPS + tap];
                float wr[18];
#pragma unroll
                for (int f = 0; f < 18; f++) wr[f] = Bs[f * TAPS + tap];
                int pp = ((n * 2 + pz) * 2 + py) * 2 + px;
                const float* base = g_v + (long long)(pp * 24) * 4913
                                  + ((z2 * 17 + y2) * 17 + x2);
#pragma unroll
                for (int u = 0; u < 8; u++) {
                    float v0 = vv ? base[(u * 3 + 0) * 4913] : 0.f;
                    float v1 = vv ? base[(u * 3 + 1) * 4913] : 0.f;
                    float v2 = vv ? base[(u * 3 + 2) * 4913] : 0.f;
#pragma unroll
                    for (int b = 0; b < 3; b++) {
                        float t = da[u * 3 + b];
                        t = fmaf(v0, ar[b * 3 + 0], t);
                        t = fmaf(v1, ar[b * 3 + 1], t);
                        t = fmaf(v2, ar[b * 3 + 2], t);
                        da[u * 3 + b] = t;
                    }
                    float p00 = v0 * v0, p11 = v1 * v1, p22 = v2 * v2;
                    float p01 = v0 * v1, p02 = v0 * v2, p12 = v1 * v2;
#pragma unroll
                    for (int b = 0; b < 3; b++) {
                        float t = db[u * 3 + b];
                        t = fmaf(p00, wr[b * 6 + 0], t);
                        t = fmaf(p11, wr[b * 6 + 1], t);
                        t = fmaf(p22, wr[b * 6 + 2], t);
                        t = fmaf(p01, wr[b * 6 + 3], t);
                        t = fmaf(p02, wr[b * 6 + 4], t);
                        t = fmaf(p12, wr[b * 6 + 5], t);
                        db[u * 3 + b] = t;
                    }
                }
            }
        }
    }

    bool valid = (ox < 19) && (oy < 19) && (oz < 19);
    float yv[16];
#pragma unroll
    for (int o = 0; o < 16; o++) {
        float r = 0.f;
#pragma unroll
        for (int u = 0; u < 8; u++)
#pragma unroll
            for (int b = 0; b < 3; b++) {
                r = fmaf(w2a[(o * 8 + u) * 3 + b], da[u * 3 + b], r);
                r = fmaf(w2b[(o * 8 + u) * 3 + b], db[u * 3 + b], r);
            }
        yv[o] = r;
    }
    if (valid) {
        long long base = (long long)(n * 16) * 6859 + (oz * 19 + oy) * 19 + ox;
#pragma unroll
        for (int o = 0; o < 16; o++) g_y[base + o * 6859] = yv[o];
    }
    // BN stats: warp butterfly reduce, then one atomic per warp per channel
#pragma unroll
    for (int o = 0; o < 16; o++) {
        float sv = valid ? yv[o] : 0.f;
        float sq = sv * sv;
#pragma unroll
        for (int off = 16; off > 0; off >>= 1) {
            sv += __shfl_xor_sync(0xffffffffu, sv, off);
            sq += __shfl_xor_sync(0xffffffffu, sq, off);
        }
        if ((tid & 31) == 0) {
            atomicAdd(&g_sum[o], sv);
            atomicAdd(&g_sumsq[o], sq);
        }
    }
}

__global__ void k_fin(const float* __restrict__ gamma, const float* __restrict__ beta,
                      const float* __restrict__ bias, float* __restrict__ out) {
    int i = blockIdx.x * 256 + threadIdx.x;        // exactly 16*16*6859 = 6859 blocks
    int o = (i / 6859) & 15;
    const float invN = 1.f / 109744.f;             // 16 * 19^3
    float mean = g_sum[o] * invN;
    float var = g_sumsq[o] * invN - mean * mean;
    float r = rsqrtf(var + 1e-5f);
    float v = (g_y[i] - mean) * r * gamma[o] + beta[o] + bias[o];
    out[i] = v > 0.f ? v : 0.f;
}

extern "C" void kernel_launch(void* const* d_in, const int* in_sizes, int n_in,
                              void* d_out, int out_size) {
    const float* s     = (const float*)d_in[0];
    const float* basis1= (const float*)d_in[1];
    const float* W1    = (const float*)d_in[2];
    const float* b2a   = (const float*)d_in[3];
    const float* b2b   = (const float*)d_in[4];
    const float* W2a   = (const float*)d_in[5];
    const float* W2b   = (const float*)d_in[6];
    const float* gamma = (const float*)d_in[7];
    const float* beta  = (const float*)d_in[8];
    const float* bias  = (const float*)d_in[9];

    k_zero<<<1, 32>>>();
    k_split<<<65536, 256>>>(s);                     // 2^24 / 256
    k_conv1<<<dim3(225, 16), 128>>>(basis1, W1);
    k_conv2<<<dim3(75, 16), 128>>>(b2a, b2b, W2a, W2b);
    k_fin<<<6859, 256>>>(gamma, beta, bias, (float*)d_out);
}